// round 4
// baseline (speedup 1.0000x reference)
#include <cuda_runtime.h>
#include <math.h>

// Model dims
#define BB   1024
#define TT   20
#define CC   512
#define HH   8
#define LL   8
#define DD   64
#define MTOK (BB * TT)   // 20480 tokens

// ---------------------------------------------------------------------------
// Scratch (device globals: no allocation allowed in kernel_launch)
// ---------------------------------------------------------------------------
__device__ float g_h  [MTOK * CC];
__device__ float g_xn [MTOK * CC];
__device__ float g_qkv[MTOK * 3 * CC];
__device__ float g_y  [MTOK * CC];
__device__ float g_mid[MTOK * 4 * CC];

// tf32-pre-rounded weights (concatenated): attn | proj | fc1 | fc2
#define WATTN_OFF 0
#define WATTN_SZ  (LL * CC * 3 * CC)          // 6,291,456
#define WPROJ_OFF (WATTN_OFF + WATTN_SZ)
#define WPROJ_SZ  (LL * CC * CC)              // 2,097,152
#define WFC1_OFF  (WPROJ_OFF + WPROJ_SZ)
#define WFC1_SZ   (LL * CC * 4 * CC)          // 8,388,608
#define WFC2_OFF  (WFC1_OFF + WFC1_SZ)
#define WFC2_SZ   (LL * 4 * CC * CC)          // 8,388,608
#define WTOTAL    (WFC2_OFF + WFC2_SZ)
__device__ float g_wt[WTOTAL];

__device__ __forceinline__ unsigned f2tf32(float f) {
    unsigned r;
    asm("cvt.rna.tf32.f32 %0, %1;" : "=r"(r) : "f"(f));
    return r;
}
__device__ __forceinline__ float round_tf32(float f) {
    return __uint_as_float(f2tf32(f));
}

// ---------------------------------------------------------------------------
// Weight pre-rounding (one pass, bandwidth-bound)
// ---------------------------------------------------------------------------
__global__ void wcvt_kernel(const float* __restrict__ src, float* __restrict__ dst, int n) {
    int i = blockIdx.x * blockDim.x + threadIdx.x;
    int stride = gridDim.x * blockDim.x;
    for (; i < n; i += stride) dst[i] = round_tf32(src[i]);
}

// ---------------------------------------------------------------------------
// Encoder: h = x @ enc_w + enc_b + wpe[t+1]   (V = 2, unrolled). h stays fp32.
// ---------------------------------------------------------------------------
__global__ void encode_kernel(const float* __restrict__ x,
                              const float* __restrict__ enc_w,
                              const float* __restrict__ enc_b,
                              const float* __restrict__ wpe,
                              float* __restrict__ out) {
    int i = blockIdx.x * blockDim.x + threadIdx.x;
    if (i >= MTOK * CC) return;
    int m = i / CC, c = i % CC;
    int t = m % TT;
    float x0 = x[m * 2 + 0], x1 = x[m * 2 + 1];
    out[i] = x0 * enc_w[c] + x1 * enc_w[CC + c] + enc_b[c] + wpe[(t + 1) * CC + c];
}

// ---------------------------------------------------------------------------
// LayerNorm: one 128-thread block per token row. Output tf32-rounded
// (it is always consumed as a GEMM A operand or by the fp32 predictor).
// ---------------------------------------------------------------------------
__global__ void ln_kernel(const float* __restrict__ in,
                          const float* __restrict__ w,
                          const float* __restrict__ b,
                          float* __restrict__ out) {
    int row = blockIdx.x;
    const float* p = in + (size_t)row * CC;
    float v[4];
    float s = 0.f, sq = 0.f;
#pragma unroll
    for (int i = 0; i < 4; i++) {
        v[i] = p[threadIdx.x + i * 128];
        s  += v[i];
        sq += v[i] * v[i];
    }
#pragma unroll
    for (int o = 16; o > 0; o >>= 1) {
        s  += __shfl_xor_sync(0xffffffff, s, o);
        sq += __shfl_xor_sync(0xffffffff, sq, o);
    }
    __shared__ float red[8];
    int warp = threadIdx.x >> 5;
    if ((threadIdx.x & 31) == 0) { red[warp] = s; red[4 + warp] = sq; }
    __syncthreads();
    s  = red[0] + red[1] + red[2] + red[3];
    sq = red[4] + red[5] + red[6] + red[7];
    float mu  = s / CC;
    float var = sq / CC - mu * mu;
    float inv = rsqrtf(var + 1e-5f);
    float* q = out + (size_t)row * CC;
#pragma unroll
    for (int i = 0; i < 4; i++) {
        int c = threadIdx.x + i * 128;
        q[c] = round_tf32((v[i] - mu) * inv * w[c] + b[c]);
    }
}

// ---------------------------------------------------------------------------
// TF32 tensor-core GEMM, inputs pre-rounded to tf32 (no CVT inside).
// 128x128 CTA tile, KT=32, 256 threads (8 warps, 2x4, 64x32 warp tiles,
// m16n8k8). A-tile stored in fragment order for LDS.128 fragment loads:
//   Asr[k][wm][g][j]  (j pitch 1, g pitch 12, wm pitch 96, k pitch 200)
//   element (k, m): wm=m>>6, g=m&7, j=(m&63)>>3
// STS banks 12g+j distinct mod 32; LDS.128 chunks 2t+3g distinct mod 8. Both
// conflict-free. B-tile k-major [KT][136], scalar frag loads (conflict-free).
// EPI: 0 = +bias, 1 = +bias,GELU,round->tf32, 2 = +bias,+residual
// ---------------------------------------------------------------------------
#define KT    32
#define AKP   200   // Asr k pitch (floats): 2*96 + 8 pad
#define AWP   96    // Asr wm pitch
#define AGP   12    // Asr g pitch (8 j + 4 pad)
#define SPAD  136   // Bs row pitch

template <int EPI>
__global__ void __launch_bounds__(256, 2)
tgemm_kernel(const float* __restrict__ A,
             const float* __restrict__ W,
             const float* __restrict__ bias,
             const float* __restrict__ res,
             float* __restrict__ out,
             int Ndim, int Kdim) {
    __shared__ float Asr[KT * AKP];
    __shared__ float Bs[KT][SPAD];

    const int bm = blockIdx.y * 128, bn = blockIdx.x * 128;
    const int tid  = threadIdx.x;
    const int lane = tid & 31;
    const int wid  = tid >> 5;
    const int g    = lane >> 2;
    const int tig  = lane & 3;
    const int warp_m = (wid >> 2) * 64;   // 0 or 64
    const int warp_n = (wid & 3) * 32;    // 0,32,64,96

    float acc[4][4][4];
#pragma unroll
    for (int mi = 0; mi < 4; mi++)
#pragma unroll
        for (int ni = 0; ni < 4; ni++)
#pragma unroll
            for (int r = 0; r < 4; r++) acc[mi][ni][r] = 0.f;

    // A load mapping: thread loads global row (tid&127), 4x float4 at k-cols
    const int a_row = tid & 127;
    const int a_c0  = (tid >> 7) * 4;
    // Per-thread fragment-order store base for row a_row:
    const int a_moff = (a_row >> 6) * AWP + (a_row & 7) * AGP + ((a_row & 63) >> 3);
    // B load mapping
    const int b_n4 = (tid & 31) * 4;
    const int b_k  = tid >> 5;

    const float* Abase = A + (size_t)(bm + a_row) * Kdim + a_c0;
    const float* Wbase = W + (size_t)b_k * Ndim + bn + b_n4;

    // Per-thread fragment-load base (k=tig component folded in):
    const int fa0 = tig * AKP + (warp_m >> 6) * AWP + g * AGP;

    for (int k0 = 0; k0 < Kdim; k0 += KT) {
        // ---- fill smem (inputs already tf32-rounded; plain copies) ----
#pragma unroll
        for (int i = 0; i < 4; i++) {
            float4 av = *(const float4*)(Abase + k0 + 8 * i);
            int kb = a_c0 + 8 * i;
            Asr[(kb + 0) * AKP + a_moff] = av.x;
            Asr[(kb + 1) * AKP + a_moff] = av.y;
            Asr[(kb + 2) * AKP + a_moff] = av.z;
            Asr[(kb + 3) * AKP + a_moff] = av.w;
        }
#pragma unroll
        for (int i = 0; i < 4; i++) {
            *(float4*)&Bs[b_k + 8 * i][b_n4] = *(const float4*)(Wbase + (size_t)(k0 + 8 * i) * Ndim);
        }
        __syncthreads();

        // ---- compute: 4 k-steps of 8 ----
#pragma unroll
        for (int ks = 0; ks < 4; ks++) {
            const int kr0 = ks * 8 + tig;
            const int kr1 = kr0 + 4;
            // A fragments: 4x LDS.128
            const int base0 = fa0 + ks * 8 * AKP;          // row kr0
            float4 v0 = *(const float4*)&Asr[base0 + 0];   // j 0..3
            float4 v1 = *(const float4*)&Asr[base0 + 4];   // j 4..7
            float4 w0 = *(const float4*)&Asr[base0 + 4 * AKP + 0];  // row kr1
            float4 w1 = *(const float4*)&Asr[base0 + 4 * AKP + 4];
            unsigned a[4][4];
            a[0][0] = __float_as_uint(v0.x); a[0][1] = __float_as_uint(v0.y);
            a[0][2] = __float_as_uint(w0.x); a[0][3] = __float_as_uint(w0.y);
            a[1][0] = __float_as_uint(v0.z); a[1][1] = __float_as_uint(v0.w);
            a[1][2] = __float_as_uint(w0.z); a[1][3] = __float_as_uint(w0.w);
            a[2][0] = __float_as_uint(v1.x); a[2][1] = __float_as_uint(v1.y);
            a[2][2] = __float_as_uint(w1.x); a[2][3] = __float_as_uint(w1.y);
            a[3][0] = __float_as_uint(v1.z); a[3][1] = __float_as_uint(v1.w);
            a[3][2] = __float_as_uint(w1.z); a[3][3] = __float_as_uint(w1.w);

            unsigned b[4][2];
#pragma unroll
            for (int ni = 0; ni < 4; ni++) {
                int n0 = warp_n + 8 * ni;
                b[ni][0] = __float_as_uint(Bs[kr0][n0 + g]);
                b[ni][1] = __float_as_uint(Bs[kr1][n0 + g]);
            }
#pragma unroll
            for (int mi = 0; mi < 4; mi++)
#pragma unroll
                for (int ni = 0; ni < 4; ni++) {
                    asm volatile(
                        "mma.sync.aligned.m16n8k8.row.col.f32.tf32.tf32.f32 "
                        "{%0,%1,%2,%3}, {%4,%5,%6,%7}, {%8,%9}, {%0,%1,%2,%3};"
                        : "+f"(acc[mi][ni][0]), "+f"(acc[mi][ni][1]),
                          "+f"(acc[mi][ni][2]), "+f"(acc[mi][ni][3])
                        : "r"(a[mi][0]), "r"(a[mi][1]), "r"(a[mi][2]), "r"(a[mi][3]),
                          "r"(b[ni][0]), "r"(b[ni][1]));
                }
        }
        __syncthreads();
    }

    // ---- epilogue ----
#pragma unroll
    for (int mi = 0; mi < 4; mi++) {
#pragma unroll
        for (int half = 0; half < 2; half++) {
            int row = bm + warp_m + 16 * mi + g + 8 * half;
            float* op = out + (size_t)row * Ndim + bn;
            const float* rp = (EPI == 2) ? (res + (size_t)row * Ndim + bn) : nullptr;
#pragma unroll
            for (int ni = 0; ni < 4; ni++) {
                int col = warp_n + 8 * ni + 2 * tig;
#pragma unroll
                for (int c = 0; c < 2; c++) {
                    float vv = acc[mi][ni][2 * half + c] + bias[bn + col + c];
                    if (EPI == 1) {
                        vv = 0.5f * vv * (1.0f + erff(vv * 0.70710678118654752440f));
                        vv = round_tf32(vv);   // feeds fc2 as A operand
                    }
                    if (EPI == 2) vv += rp[col + c];
                    op[col + c] = vv;
                }
            }
        }
    }
}

// ---------------------------------------------------------------------------
// Attention: one 128-thread block per (batch, head). Rows padded to DD+1
// (removes the 20-way K/V bank conflicts). Output tf32-rounded (feeds proj A).
// ---------------------------------------------------------------------------
__global__ void attn_kernel(const float* __restrict__ qkv, float* __restrict__ y) {
    __shared__ float Q[TT][DD + 1], K[TT][DD + 1], V[TT][DD + 1], S[TT][TT + 1];
    int b = blockIdx.x / HH, h = blockIdx.x % HH;
    const float* base = qkv + (size_t)b * TT * 3 * CC + h * DD;

    for (int idx = threadIdx.x; idx < TT * DD; idx += blockDim.x) {
        int t = idx / DD, d = idx % DD;
        const float* p = base + (size_t)t * 3 * CC + d;
        Q[t][d] = p[0];
        K[t][d] = p[CC];
        V[t][d] = p[2 * CC];
    }
    __syncthreads();

    const float scale = 0.125f;
    for (int idx = threadIdx.x; idx < TT * TT; idx += blockDim.x) {
        int tq = idx / TT, tk = idx % TT;
        if (tk <= tq) {
            float s = 0.f;
#pragma unroll
            for (int d = 0; d < DD; d++) s += Q[tq][d] * K[tk][d];
            S[tq][tk] = s * scale;
        }
    }
    __syncthreads();

    if (threadIdx.x < TT) {
        int tq = threadIdx.x;
        float mx = -1e30f;
        for (int tk = 0; tk <= tq; tk++) mx = fmaxf(mx, S[tq][tk]);
        float sum = 0.f;
        for (int tk = 0; tk <= tq; tk++) {
            float e = expf(S[tq][tk] - mx);
            S[tq][tk] = e;
            sum += e;
        }
        float inv = 1.f / sum;
        for (int tk = 0; tk <= tq; tk++) S[tq][tk] *= inv;
    }
    __syncthreads();

    for (int idx = threadIdx.x; idx < TT * DD; idx += blockDim.x) {
        int t = idx / DD, d = idx % DD;
        float o = 0.f;
        for (int tk = 0; tk <= t; tk++) o += S[t][tk] * V[tk][d];
        y[((size_t)b * TT + t) * CC + h * DD + d] = round_tf32(o);
    }
}

// ---------------------------------------------------------------------------
// Predictor: out[m, v] = xn[m,:] . pred_w[:, v] + pred_b[v], V = 2.
// ---------------------------------------------------------------------------
__global__ void pred_kernel(const float* __restrict__ xn,
                            const float* __restrict__ pw,
                            const float* __restrict__ pb,
                            float* __restrict__ out) {
    int m = blockIdx.x * 4 + (threadIdx.x >> 5);
    int lane = threadIdx.x & 31;
    const float* p = xn + (size_t)m * CC;
    float a0 = 0.f, a1 = 0.f;
    for (int c = lane; c < CC; c += 32) {
        float v = p[c];
        a0 += v * pw[c * 2 + 0];
        a1 += v * pw[c * 2 + 1];
    }
#pragma unroll
    for (int o = 16; o > 0; o >>= 1) {
        a0 += __shfl_xor_sync(0xffffffff, a0, o);
        a1 += __shfl_xor_sync(0xffffffff, a1, o);
    }
    if (lane == 0) {
        out[m * 2 + 0] = a0 + pb[0];
        out[m * 2 + 1] = a1 + pb[1];
    }
}

// ---------------------------------------------------------------------------
// Launch
// ---------------------------------------------------------------------------
extern "C" void kernel_launch(void* const* d_in, const int* in_sizes, int n_in,
                              void* d_out, int out_size) {
    const float* x      = (const float*)d_in[0];
    const float* enc_w  = (const float*)d_in[1];
    const float* enc_b  = (const float*)d_in[2];
    const float* wpe    = (const float*)d_in[3];
    const float* ln1_w  = (const float*)d_in[4];
    const float* ln1_b  = (const float*)d_in[5];
    const float* attn_w = (const float*)d_in[6];
    const float* attn_b = (const float*)d_in[7];
    const float* proj_w = (const float*)d_in[8];
    const float* proj_b = (const float*)d_in[9];
    const float* ln2_w  = (const float*)d_in[10];
    const float* ln2_b  = (const float*)d_in[11];
    const float* fc1_w  = (const float*)d_in[12];
    const float* fc1_b  = (const float*)d_in[13];
    const float* fc2_w  = (const float*)d_in[14];
    const float* fc2_b  = (const float*)d_in[15];
    const float* lnf_w  = (const float*)d_in[16];
    const float* lnf_b  = (const float*)d_in[17];
    const float* pred_w = (const float*)d_in[18];
    const float* pred_b = (const float*)d_in[19];

    float *h, *xn, *qkv, *y, *mid, *wt;
    cudaGetSymbolAddress((void**)&h,   g_h);
    cudaGetSymbolAddress((void**)&xn,  g_xn);
    cudaGetSymbolAddress((void**)&qkv, g_qkv);
    cudaGetSymbolAddress((void**)&y,   g_y);
    cudaGetSymbolAddress((void**)&mid, g_mid);
    cudaGetSymbolAddress((void**)&wt,  g_wt);

    // Pre-round weights to tf32 (bandwidth-bound, ~40us total)
    wcvt_kernel<<<592, 256>>>(attn_w, wt + WATTN_OFF, WATTN_SZ);
    wcvt_kernel<<<592, 256>>>(proj_w, wt + WPROJ_OFF, WPROJ_SZ);
    wcvt_kernel<<<592, 256>>>(fc1_w,  wt + WFC1_OFF,  WFC1_SZ);
    wcvt_kernel<<<592, 256>>>(fc2_w,  wt + WFC2_OFF,  WFC2_SZ);

    encode_kernel<<<(MTOK * CC + 255) / 256, 256>>>(x, enc_w, enc_b, wpe, h);

    dim3 gQKV(3 * CC / 128, MTOK / 128);   // 12 x 160
    dim3 gC  (CC / 128,     MTOK / 128);   //  4 x 160
    dim3 gFC1(4 * CC / 128, MTOK / 128);   // 16 x 160

    for (int l = 0; l < LL; l++) {
        ln_kernel<<<MTOK, 128>>>(h, ln1_w + l * CC, ln1_b + l * CC, xn);
        tgemm_kernel<0><<<gQKV, 256>>>(xn, wt + WATTN_OFF + (size_t)l * CC * 3 * CC,
                                       attn_b + (size_t)l * 3 * CC, nullptr, qkv,
                                       3 * CC, CC);
        attn_kernel<<<BB * HH, 128>>>(qkv, y);
        tgemm_kernel<2><<<gC, 256>>>(y, wt + WPROJ_OFF + (size_t)l * CC * CC,
                                     proj_b + (size_t)l * CC, h, h, CC, CC);
        ln_kernel<<<MTOK, 128>>>(h, ln2_w + l * CC, ln2_b + l * CC, xn);
        tgemm_kernel<1><<<gFC1, 256>>>(xn, wt + WFC1_OFF + (size_t)l * CC * 4 * CC,
                                       fc1_b + (size_t)l * 4 * CC, nullptr, mid,
                                       4 * CC, CC);
        tgemm_kernel<2><<<gC, 256>>>(mid, wt + WFC2_OFF + (size_t)l * 4 * CC * CC,
                                     fc2_b + (size_t)l * CC, h, h, CC, 4 * CC);
    }

    ln_kernel<<<MTOK, 128>>>(h, lnf_w, lnf_b, xn);
    pred_kernel<<<MTOK / 4, 128>>>(xn, pred_w, pred_b, (float*)d_out);
}

// round 7
// speedup vs baseline: 1.2421x; 1.2421x over previous
#include <cuda_runtime.h>
#include <math.h>

// Model dims
#define BB   1024
#define TT   20
#define CC   512
#define HH   8
#define LL   8
#define DD   64
#define MTOK (BB * TT)   // 20480 tokens

// ---------------------------------------------------------------------------
// Scratch (device globals: no allocation allowed in kernel_launch)
// ---------------------------------------------------------------------------
__device__ float g_h  [MTOK * CC];
__device__ float g_xn [MTOK * CC];
__device__ float g_qkv[MTOK * 3 * CC];
__device__ float g_y  [MTOK * CC];
__device__ float g_mid[MTOK * 4 * CC];

// tf32-pre-rounded weights (concatenated): attn | proj | fc1 | fc2
#define WATTN_OFF 0
#define WATTN_SZ  (LL * CC * 3 * CC)
#define WPROJ_OFF (WATTN_OFF + WATTN_SZ)
#define WPROJ_SZ  (LL * CC * CC)
#define WFC1_OFF  (WPROJ_OFF + WPROJ_SZ)
#define WFC1_SZ   (LL * CC * 4 * CC)
#define WFC2_OFF  (WFC1_OFF + WFC1_SZ)
#define WFC2_SZ   (LL * 4 * CC * CC)
#define WTOTAL    (WFC2_OFF + WFC2_SZ)
__device__ float g_wt[WTOTAL];

__device__ __forceinline__ unsigned f2tf32(float f) {
    unsigned r;
    asm("cvt.rna.tf32.f32 %0, %1;" : "=r"(r) : "f"(f));
    return r;
}
__device__ __forceinline__ float round_tf32(float f) {
    return __uint_as_float(f2tf32(f));
}

__device__ __forceinline__ void cpa16(unsigned dst, const float* src) {
    asm volatile("cp.async.cg.shared.global [%0], [%1], 16;\n" :: "r"(dst), "l"(src));
}
#define CPA_COMMIT() asm volatile("cp.async.commit_group;\n" ::: "memory")
#define CPA_WAIT0()  asm volatile("cp.async.wait_group 0;\n" ::: "memory")

// ---------------------------------------------------------------------------
// Weight pre-rounding (single launch so ncu's skip lands on a tgemm)
// ---------------------------------------------------------------------------
__global__ void wcvt_all_kernel(const float* __restrict__ aw,
                                const float* __restrict__ pw,
                                const float* __restrict__ f1,
                                const float* __restrict__ f2,
                                float* __restrict__ dst) {
    int i = blockIdx.x * blockDim.x + threadIdx.x;
    int stride = gridDim.x * blockDim.x;
    for (; i < WTOTAL; i += stride) {
        float v;
        if (i < WPROJ_OFF)      v = aw[i - WATTN_OFF];
        else if (i < WFC1_OFF)  v = pw[i - WPROJ_OFF];
        else if (i < WFC2_OFF)  v = f1[i - WFC1_OFF];
        else                    v = f2[i - WFC2_OFF];
        dst[i] = round_tf32(v);
    }
}

// ---------------------------------------------------------------------------
// Encoder: h = x @ enc_w + enc_b + wpe[t+1]
// ---------------------------------------------------------------------------
__global__ void encode_kernel(const float* __restrict__ x,
                              const float* __restrict__ enc_w,
                              const float* __restrict__ enc_b,
                              const float* __restrict__ wpe,
                              float* __restrict__ out) {
    int i = blockIdx.x * blockDim.x + threadIdx.x;
    if (i >= MTOK * CC) return;
    int m = i / CC, c = i % CC;
    int t = m % TT;
    float x0 = x[m * 2 + 0], x1 = x[m * 2 + 1];
    out[i] = x0 * enc_w[c] + x1 * enc_w[CC + c] + enc_b[c] + wpe[(t + 1) * CC + c];
}

// ---------------------------------------------------------------------------
// LayerNorm: one 128-thread block per token row; output tf32-rounded.
// ---------------------------------------------------------------------------
__global__ void ln_kernel(const float* __restrict__ in,
                          const float* __restrict__ w,
                          const float* __restrict__ b,
                          float* __restrict__ out) {
    int row = blockIdx.x;
    const float* p = in + (size_t)row * CC;
    float v[4];
    float s = 0.f, sq = 0.f;
#pragma unroll
    for (int i = 0; i < 4; i++) {
        v[i] = p[threadIdx.x + i * 128];
        s  += v[i];
        sq += v[i] * v[i];
    }
#pragma unroll
    for (int o = 16; o > 0; o >>= 1) {
        s  += __shfl_xor_sync(0xffffffff, s, o);
        sq += __shfl_xor_sync(0xffffffff, sq, o);
    }
    __shared__ float red[8];
    int warp = threadIdx.x >> 5;
    if ((threadIdx.x & 31) == 0) { red[warp] = s; red[4 + warp] = sq; }
    __syncthreads();
    s  = red[0] + red[1] + red[2] + red[3];
    sq = red[4] + red[5] + red[6] + red[7];
    float mu  = s / CC;
    float var = sq / CC - mu * mu;
    float inv = rsqrtf(var + 1e-5f);
    float* q = out + (size_t)row * CC;
#pragma unroll
    for (int i = 0; i < 4; i++) {
        int c = threadIdx.x + i * 128;
        q[c] = round_tf32((v[i] - mu) * inv * w[c] + b[c]);
    }
}

// ---------------------------------------------------------------------------
// TF32 tensor-core GEMM, cp.async double-buffered (2-stage pipeline).
// 128x128 CTA tile, KT=32, 256 threads, 8 warps (2x4), 64x32 warp tiles,
// m16n8k8. Inputs pre-rounded to tf32.
// Smem (dynamic): As[2][128][36]  (row-major, pitch 36: frag banks = lane),
//                 Bs[2][32][136]  (k-major rows of 128 floats).
// Per k-tile: wait_group 0 -> barrier -> prefetch(t+1) -> compute(t).
// EPI: 0 = +bias, 1 = +bias,GELU,round->tf32, 2 = +bias,+residual
// ---------------------------------------------------------------------------
#define KT    32
#define APITCH 36
#define BPITCH 136
#define ASZ   (128 * APITCH)        // floats per A buffer (4608)
#define BSZ   (KT * BPITCH)         // floats per B buffer (4352)
#define SMEM_FLOATS (2 * (ASZ + BSZ))   // 17920 floats = 71680 B

template <int EPI>
__global__ void __launch_bounds__(256, 2)
tgemm_kernel(const float* __restrict__ A,
             const float* __restrict__ W,
             const float* __restrict__ bias,
             const float* __restrict__ res,
             float* __restrict__ out,
             int Ndim, int Kdim) {
    extern __shared__ float smem[];
    float* Abuf[2] = { smem, smem + ASZ };
    float* Bbuf[2] = { smem + 2 * ASZ, smem + 2 * ASZ + BSZ };

    const int bm = blockIdx.y * 128, bn = blockIdx.x * 128;
    const int tid  = threadIdx.x;
    const int lane = tid & 31;
    const int wid  = tid >> 5;
    const int g    = lane >> 2;
    const int tig  = lane & 3;
    const int warp_m = (wid >> 2) * 64;
    const int warp_n = (wid & 3) * 32;

    float acc[4][4][4];
#pragma unroll
    for (int mi = 0; mi < 4; mi++)
#pragma unroll
        for (int ni = 0; ni < 4; ni++)
#pragma unroll
            for (int r = 0; r < 4; r++) acc[mi][ni][r] = 0.f;

    // --- prefetch mappings ---
    // A: thread -> row r = tid/2, float-cols cb + 4i, cb = (tid&1)*16
    const int a_r  = tid >> 1;
    const int a_cb = (tid & 1) * 16;
    const float* Ag = A + (size_t)(bm + a_r) * Kdim + a_cb;
    // B: chunks ch = tid + 256*i ; k = ch/32, c = ch%32 (4-float chunks)
    const float* Wg = W + bn;

    unsigned aS[2], bS[2];
    aS[0] = (unsigned)__cvta_generic_to_shared(Abuf[0]);
    aS[1] = (unsigned)__cvta_generic_to_shared(Abuf[1]);
    bS[0] = (unsigned)__cvta_generic_to_shared(Bbuf[0]);
    bS[1] = (unsigned)__cvta_generic_to_shared(Bbuf[1]);

    const int NT = Kdim / KT;

    // prefetch tile 0 into buffer 0
    {
        const float* as = Ag;
        unsigned ad = aS[0] + (a_r * APITCH + a_cb) * 4;
#pragma unroll
        for (int i = 0; i < 4; i++) cpa16(ad + 16 * i, as + 4 * i);
#pragma unroll
        for (int i = 0; i < 4; i++) {
            int ch = tid + 256 * i;
            int k = ch >> 5, c = ch & 31;
            cpa16(bS[0] + (k * BPITCH + c * 4) * 4, Wg + (size_t)k * Ndim + c * 4);
        }
        CPA_COMMIT();
    }

    for (int t = 0; t < NT; t++) {
        CPA_WAIT0();
        __syncthreads();

        // prefetch tile t+1 into the other buffer (overlaps with compute)
        if (t + 1 < NT) {
            int nb = (t + 1) & 1;
            int k0 = (t + 1) * KT;
            const float* as = Ag + k0;
            unsigned ad = aS[nb] + (a_r * APITCH + a_cb) * 4;
#pragma unroll
            for (int i = 0; i < 4; i++) cpa16(ad + 16 * i, as + 4 * i);
#pragma unroll
            for (int i = 0; i < 4; i++) {
                int ch = tid + 256 * i;
                int k = ch >> 5, c = ch & 31;
                cpa16(bS[nb] + (k * BPITCH + c * 4) * 4,
                      Wg + (size_t)(k0 + k) * Ndim + c * 4);
            }
            CPA_COMMIT();
        }

        // compute tile t
        const float* As = Abuf[t & 1];
        const float* Bs = Bbuf[t & 1];
#pragma unroll
        for (int ks = 0; ks < 4; ks++) {
            const int kr0 = ks * 8 + tig;
            const int kr1 = kr0 + 4;
            unsigned a[4][4], b[4][2];
#pragma unroll
            for (int mi = 0; mi < 4; mi++) {
                int m = warp_m + 16 * mi + g;
                a[mi][0] = __float_as_uint(As[m * APITCH + kr0]);
                a[mi][1] = __float_as_uint(As[(m + 8) * APITCH + kr0]);
                a[mi][2] = __float_as_uint(As[m * APITCH + kr1]);
                a[mi][3] = __float_as_uint(As[(m + 8) * APITCH + kr1]);
            }
#pragma unroll
            for (int ni = 0; ni < 4; ni++) {
                int n0 = warp_n + 8 * ni + g;
                b[ni][0] = __float_as_uint(Bs[kr0 * BPITCH + n0]);
                b[ni][1] = __float_as_uint(Bs[kr1 * BPITCH + n0]);
            }
#pragma unroll
            for (int mi = 0; mi < 4; mi++)
#pragma unroll
                for (int ni = 0; ni < 4; ni++) {
                    asm volatile(
                        "mma.sync.aligned.m16n8k8.row.col.f32.tf32.tf32.f32 "
                        "{%0,%1,%2,%3}, {%4,%5,%6,%7}, {%8,%9}, {%0,%1,%2,%3};"
                        : "+f"(acc[mi][ni][0]), "+f"(acc[mi][ni][1]),
                          "+f"(acc[mi][ni][2]), "+f"(acc[mi][ni][3])
                        : "r"(a[mi][0]), "r"(a[mi][1]), "r"(a[mi][2]), "r"(a[mi][3]),
                          "r"(b[ni][0]), "r"(b[ni][1]));
                }
        }
    }

    // ---- epilogue ----
#pragma unroll
    for (int mi = 0; mi < 4; mi++) {
#pragma unroll
        for (int half = 0; half < 2; half++) {
            int row = bm + warp_m + 16 * mi + g + 8 * half;
            float* op = out + (size_t)row * Ndim + bn;
            const float* rp = (EPI == 2) ? (res + (size_t)row * Ndim + bn) : nullptr;
#pragma unroll
            for (int ni = 0; ni < 4; ni++) {
                int col = warp_n + 8 * ni + 2 * tig;
#pragma unroll
                for (int c = 0; c < 2; c++) {
                    float vv = acc[mi][ni][2 * half + c] + bias[bn + col + c];
                    if (EPI == 1) {
                        vv = 0.5f * vv * (1.0f + erff(vv * 0.70710678118654752440f));
                        vv = round_tf32(vv);
                    }
                    if (EPI == 2) vv += rp[col + c];
                    op[col + c] = vv;
                }
            }
        }
    }
}

// ---------------------------------------------------------------------------
// Attention: one 128-thread block per (batch, head); padded rows.
// ---------------------------------------------------------------------------
__global__ void attn_kernel(const float* __restrict__ qkv, float* __restrict__ y) {
    __shared__ float Q[TT][DD + 1], K[TT][DD + 1], V[TT][DD + 1], S[TT][TT + 1];
    int b = blockIdx.x / HH, h = blockIdx.x % HH;
    const float* base = qkv + (size_t)b * TT * 3 * CC + h * DD;

    for (int idx = threadIdx.x; idx < TT * DD; idx += blockDim.x) {
        int t = idx / DD, d = idx % DD;
        const float* p = base + (size_t)t * 3 * CC + d;
        Q[t][d] = p[0];
        K[t][d] = p[CC];
        V[t][d] = p[2 * CC];
    }
    __syncthreads();

    const float scale = 0.125f;
    for (int idx = threadIdx.x; idx < TT * TT; idx += blockDim.x) {
        int tq = idx / TT, tk = idx % TT;
        if (tk <= tq) {
            float s = 0.f;
#pragma unroll
            for (int d = 0; d < DD; d++) s += Q[tq][d] * K[tk][d];
            S[tq][tk] = s * scale;
        }
    }
    __syncthreads();

    if (threadIdx.x < TT) {
        int tq = threadIdx.x;
        float mx = -1e30f;
        for (int tk = 0; tk <= tq; tk++) mx = fmaxf(mx, S[tq][tk]);
        float sum = 0.f;
        for (int tk = 0; tk <= tq; tk++) {
            float e = expf(S[tq][tk] - mx);
            S[tq][tk] = e;
            sum += e;
        }
        float inv = 1.f / sum;
        for (int tk = 0; tk <= tq; tk++) S[tq][tk] *= inv;
    }
    __syncthreads();

    for (int idx = threadIdx.x; idx < TT * DD; idx += blockDim.x) {
        int t = idx / DD, d = idx % DD;
        float o = 0.f;
        for (int tk = 0; tk <= t; tk++) o += S[t][tk] * V[tk][d];
        y[((size_t)b * TT + t) * CC + h * DD + d] = round_tf32(o);
    }
}

// ---------------------------------------------------------------------------
// Predictor
// ---------------------------------------------------------------------------
__global__ void pred_kernel(const float* __restrict__ xn,
                            const float* __restrict__ pw,
                            const float* __restrict__ pb,
                            float* __restrict__ out) {
    int m = blockIdx.x * 4 + (threadIdx.x >> 5);
    int lane = threadIdx.x & 31;
    const float* p = xn + (size_t)m * CC;
    float a0 = 0.f, a1 = 0.f;
    for (int c = lane; c < CC; c += 32) {
        float v = p[c];
        a0 += v * pw[c * 2 + 0];
        a1 += v * pw[c * 2 + 1];
    }
#pragma unroll
    for (int o = 16; o > 0; o >>= 1) {
        a0 += __shfl_xor_sync(0xffffffff, a0, o);
        a1 += __shfl_xor_sync(0xffffffff, a1, o);
    }
    if (lane == 0) {
        out[m * 2 + 0] = a0 + pb[0];
        out[m * 2 + 1] = a1 + pb[1];
    }
}

// ---------------------------------------------------------------------------
// Launch
// ---------------------------------------------------------------------------
extern "C" void kernel_launch(void* const* d_in, const int* in_sizes, int n_in,
                              void* d_out, int out_size) {
    const float* x      = (const float*)d_in[0];
    const float* enc_w  = (const float*)d_in[1];
    const float* enc_b  = (const float*)d_in[2];
    const float* wpe    = (const float*)d_in[3];
    const float* ln1_w  = (const float*)d_in[4];
    const float* ln1_b  = (const float*)d_in[5];
    const float* attn_w = (const float*)d_in[6];
    const float* attn_b = (const float*)d_in[7];
    const float* proj_w = (const float*)d_in[8];
    const float* proj_b = (const float*)d_in[9];
    const float* ln2_w  = (const float*)d_in[10];
    const float* ln2_b  = (const float*)d_in[11];
    const float* fc1_w  = (const float*)d_in[12];
    const float* fc1_b  = (const float*)d_in[13];
    const float* fc2_w  = (const float*)d_in[14];
    const float* fc2_b  = (const float*)d_in[15];
    const float* lnf_w  = (const float*)d_in[16];
    const float* lnf_b  = (const float*)d_in[17];
    const float* pred_w = (const float*)d_in[18];
    const float* pred_b = (const float*)d_in[19];

    float *h, *xn, *qkv, *y, *mid, *wt;
    cudaGetSymbolAddress((void**)&h,   g_h);
    cudaGetSymbolAddress((void**)&xn,  g_xn);
    cudaGetSymbolAddress((void**)&qkv, g_qkv);
    cudaGetSymbolAddress((void**)&y,   g_y);
    cudaGetSymbolAddress((void**)&mid, g_mid);
    cudaGetSymbolAddress((void**)&wt,  g_wt);

    const int smem_bytes = SMEM_FLOATS * 4;   // 71680
    // Unconditional (no static guards allowed); host-side, capture-safe.
    cudaFuncSetAttribute(tgemm_kernel<0>, cudaFuncAttributeMaxDynamicSharedMemorySize, smem_bytes);
    cudaFuncSetAttribute(tgemm_kernel<1>, cudaFuncAttributeMaxDynamicSharedMemorySize, smem_bytes);
    cudaFuncSetAttribute(tgemm_kernel<2>, cudaFuncAttributeMaxDynamicSharedMemorySize, smem_bytes);

    // launch 0: weight pre-round (single launch)
    wcvt_all_kernel<<<1184, 256>>>(attn_w, proj_w, fc1_w, fc2_w, wt);
    // launch 1
    encode_kernel<<<(MTOK * CC + 255) / 256, 256>>>(x, enc_w, enc_b, wpe, h);

    dim3 gQKV(3 * CC / 128, MTOK / 128);
    dim3 gC  (CC / 128,     MTOK / 128);
    dim3 gFC1(4 * CC / 128, MTOK / 128);

    for (int l = 0; l < LL; l++) {
        ln_kernel<<<MTOK, 128>>>(h, ln1_w + l * CC, ln1_b + l * CC, xn);
        tgemm_kernel<0><<<gQKV, 256, smem_bytes>>>(xn, wt + WATTN_OFF + (size_t)l * CC * 3 * CC,
                                       attn_b + (size_t)l * 3 * CC, nullptr, qkv,
                                       3 * CC, CC);
        attn_kernel<<<BB * HH, 128>>>(qkv, y);
        tgemm_kernel<2><<<gC, 256, smem_bytes>>>(y, wt + WPROJ_OFF + (size_t)l * CC * CC,
                                     proj_b + (size_t)l * CC, h, h, CC, CC);
        ln_kernel<<<MTOK, 128>>>(h, ln2_w + l * CC, ln2_b + l * CC, xn);
        tgemm_kernel<1><<<gFC1, 256, smem_bytes>>>(xn, wt + WFC1_OFF + (size_t)l * CC * 4 * CC,
                                       fc1_b + (size_t)l * 4 * CC, nullptr, mid,
                                       4 * CC, CC);
        tgemm_kernel<2><<<gC, 256, smem_bytes>>>(mid, wt + WFC2_OFF + (size_t)l * 4 * CC * CC,
                                     fc2_b + (size_t)l * CC, h, h, CC, 4 * CC);
    }

    ln_kernel<<<MTOK, 128>>>(h, lnf_w, lnf_b, xn);
    pred_kernel<<<MTOK / 4, 128>>>(xn, pred_w, pred_b, (float*)d_out);
}

// round 12
// speedup vs baseline: 2.6699x; 2.1495x over previous
#include <cuda_runtime.h>
#include <cuda_fp16.h>
#include <math.h>
#include <stdint.h>

// Model dims
#define BB   1024
#define TT   20
#define CC   512
#define HH   8
#define LL   8
#define DD   64
#define MTOK (BB * TT)   // 20480 tokens

// ---------------------------------------------------------------------------
// Scratch (device globals: no allocation allowed in kernel_launch)
// ---------------------------------------------------------------------------
__device__ float  g_h  [MTOK * CC];          // residual (fp32)
__device__ __half g_xn [MTOK * CC];          // LN output (fp16)
__device__ float  g_qkv[MTOK * 3 * CC];      // qkv (fp32, attn input)
__device__ __half g_y  [MTOK * CC];          // attn output (fp16)
__device__ __half g_mid[MTOK * 4 * CC];      // GELU output (fp16)

// fp16, TRANSPOSED weights [N][K] per layer: attn | proj | fc1 | fc2
#define WATTN_OFF 0
#define WATTN_SZ  (LL * CC * 3 * CC)
#define WPROJ_OFF (WATTN_OFF + WATTN_SZ)
#define WPROJ_SZ  (LL * CC * CC)
#define WFC1_OFF  (WPROJ_OFF + WPROJ_SZ)
#define WFC1_SZ   (LL * CC * 4 * CC)
#define WFC2_OFF  (WFC1_OFF + WFC1_SZ)
#define WFC2_SZ   (LL * 4 * CC * CC)
#define WTOTAL    (WFC2_OFF + WFC2_SZ)
__device__ __half g_wt[WTOTAL];

__device__ __forceinline__ void cpa16(unsigned dst, const void* src) {
    asm volatile("cp.async.cg.shared.global [%0], [%1], 16;\n" :: "r"(dst), "l"(src));
}
#define CPA_COMMIT() asm volatile("cp.async.commit_group;\n" ::: "memory")
#define CPA_WAIT0()  asm volatile("cp.async.wait_group 0;\n" ::: "memory")

__device__ __forceinline__ uint32_t sm_u32(const void* p) {
    uint32_t a;
    asm("{ .reg .u64 t; cvta.to.shared.u64 t, %1; cvt.u32.u64 %0, t; }" : "=r"(a) : "l"(p));
    return a;
}
__device__ __forceinline__ void ldm_x4(uint32_t& r0, uint32_t& r1, uint32_t& r2,
                                       uint32_t& r3, uint32_t addr) {
    asm volatile("ldmatrix.sync.aligned.m8n8.x4.shared.b16 {%0,%1,%2,%3}, [%4];"
                 : "=r"(r0), "=r"(r1), "=r"(r2), "=r"(r3) : "r"(addr));
}

// ---------------------------------------------------------------------------
// Weight transpose + fp16 convert: src [K,N] fp32 -> dst [N,K] fp16.
// z: 0-7 qkv, 8-15 proj, 16-23 fc1, 24-31 fc2.
// ---------------------------------------------------------------------------
__global__ void wtrans_kernel(const float* __restrict__ aw,
                              const float* __restrict__ pw,
                              const float* __restrict__ f1,
                              const float* __restrict__ f2,
                              __half* __restrict__ dst) {
    __shared__ float tile[32][33];
    int type = blockIdx.z >> 3, l = blockIdx.z & 7;
    const float* src; __half* out; int K, N;
    if (type == 0)      { K = CC;     N = 3 * CC; src = aw + (size_t)l * K * N; out = dst + WATTN_OFF + (size_t)l * K * N; }
    else if (type == 1) { K = CC;     N = CC;     src = pw + (size_t)l * K * N; out = dst + WPROJ_OFF + (size_t)l * K * N; }
    else if (type == 2) { K = CC;     N = 4 * CC; src = f1 + (size_t)l * K * N; out = dst + WFC1_OFF  + (size_t)l * K * N; }
    else                { K = 4 * CC; N = CC;     src = f2 + (size_t)l * K * N; out = dst + WFC2_OFF  + (size_t)l * K * N; }
    int bx = blockIdx.x, by = blockIdx.y;
    if (bx * 32 >= N || by * 32 >= K) return;
    int tx = threadIdx.x, ty = threadIdx.y;   // 32 x 8
#pragma unroll
    for (int j = 0; j < 32; j += 8) {
        int k = by * 32 + ty + j, n = bx * 32 + tx;
        tile[ty + j][tx] = src[(size_t)k * N + n];
    }
    __syncthreads();
#pragma unroll
    for (int j = 0; j < 32; j += 8) {
        int n = bx * 32 + ty + j, k = by * 32 + tx;
        out[(size_t)n * K + k] = __float2half(tile[tx][ty + j]);
    }
}

// ---------------------------------------------------------------------------
// Encoder: h = x @ enc_w + enc_b + wpe[t+1]  (fp32)
// ---------------------------------------------------------------------------
__global__ void encode_kernel(const float* __restrict__ x,
                              const float* __restrict__ enc_w,
                              const float* __restrict__ enc_b,
                              const float* __restrict__ wpe,
                              float* __restrict__ out) {
    int i = blockIdx.x * blockDim.x + threadIdx.x;
    if (i >= MTOK * CC) return;
    int m = i / CC, c = i % CC;
    int t = m % TT;
    float x0 = x[m * 2 + 0], x1 = x[m * 2 + 1];
    out[i] = x0 * enc_w[c] + x1 * enc_w[CC + c] + enc_b[c] + wpe[(t + 1) * CC + c];
}

// ---------------------------------------------------------------------------
// LayerNorm: fp32 in, fp16 out (GEMM A operand / predictor input).
// ---------------------------------------------------------------------------
__global__ void ln_kernel(const float* __restrict__ in,
                          const float* __restrict__ w,
                          const float* __restrict__ b,
                          __half* __restrict__ out) {
    int row = blockIdx.x;
    const float* p = in + (size_t)row * CC;
    float v[4];
    float s = 0.f, sq = 0.f;
#pragma unroll
    for (int i = 0; i < 4; i++) {
        v[i] = p[threadIdx.x + i * 128];
        s  += v[i];
        sq += v[i] * v[i];
    }
#pragma unroll
    for (int o = 16; o > 0; o >>= 1) {
        s  += __shfl_xor_sync(0xffffffff, s, o);
        sq += __shfl_xor_sync(0xffffffff, sq, o);
    }
    __shared__ float red[8];
    int warp = threadIdx.x >> 5;
    if ((threadIdx.x & 31) == 0) { red[warp] = s; red[4 + warp] = sq; }
    __syncthreads();
    s  = red[0] + red[1] + red[2] + red[3];
    sq = red[4] + red[5] + red[6] + red[7];
    float mu  = s / CC;
    float var = sq / CC - mu * mu;
    float inv = rsqrtf(var + 1e-5f);
    __half* q = out + (size_t)row * CC;
#pragma unroll
    for (int i = 0; i < 4; i++) {
        int c = threadIdx.x + i * 128;
        q[c] = __float2half((v[i] - mu) * inv * w[c] + b[c]);
    }
}

// ---------------------------------------------------------------------------
// fp16 tensor-core GEMM (mma.sync m16n8k16, fp32 accum).
// CTA tile 128x128, KT=64, 256 threads, 8 warps (2x4), 64x32 warp tiles.
// A [M,K] fp16 row-major; Wt [N,K] fp16 row-major (pre-transposed).
// Smem: per tile 128 rows x 64 halves (128B rows), 16B chunks XOR-swizzled
//   byte(r,c16) = r*128 + ((c16 ^ (r&7))*16)   -> cp.async stores and
//   ldmatrix phases both conflict-free. Double-buffered (4 x 16KB).
// EPI: 0 = +bias -> fp32 out; 1 = +bias,GELU -> fp16 out; 2 = +bias,+res -> fp32.
// ---------------------------------------------------------------------------
#define KTT 64
#define HG_SMEM (4 * 16384 + 64)

template <int EPI>
__global__ void __launch_bounds__(256, 2)
hgemm_kernel(const __half* __restrict__ A,
             const __half* __restrict__ Wt,
             const float* __restrict__ bias,
             const float* __restrict__ res,
             void* __restrict__ outv,
             int Ndim, int Kdim) {
    extern __shared__ __align__(128) unsigned char hsm[];
    const uint32_t base = sm_u32(hsm);
    const uint32_t aS[2] = { base,         base + 16384 };
    const uint32_t bS[2] = { base + 32768, base + 49152 };

    const int bm = blockIdx.y * 128, bn = blockIdx.x * 128;
    const int tid  = threadIdx.x;
    const int lane = tid & 31;
    const int wid  = tid >> 5;
    const int warp_m = (wid >> 2) * 64;   // 0 or 64
    const int warp_n = (wid & 3) * 32;    // 0,32,64,96
    const int NT = Kdim / KTT;

    float acc[4][4][4];
#pragma unroll
    for (int mi = 0; mi < 4; mi++)
#pragma unroll
        for (int ni = 0; ni < 4; ni++)
#pragma unroll
            for (int r = 0; r < 4; r++) acc[mi][ni][r] = 0.f;

    // cp.async mapping: idx = tid + 256*i (i<4): r = idx>>3, c16 = idx&7
    const int ld_r = tid >> 3;          // rows 0..31, +32 per i
    const int ld_c = tid & 7;

    // ldmatrix per-lane constants
    const int slot = lane >> 3, lr = lane & 7;
    const int da = slot >> 1;                                   // A: chunk parity
    const uint32_t rowA_b = (uint32_t)(warp_m + ((slot & 1) << 3) + lr) * 128;
    const int db = slot & 1;                                    // B: chunk parity
    const uint32_t rowB_b = (uint32_t)(warp_n + ((slot >> 1) << 3) + lr) * 128;

    auto load_tile = [&](int t, int bsel) {
        int k0 = t * KTT;
#pragma unroll
        for (int i = 0; i < 4; i++) {
            int r = ld_r + 32 * i;
            uint32_t doff = (uint32_t)(r * 128 + ((ld_c ^ (r & 7)) * 16));
            cpa16(aS[bsel] + doff, A  + (size_t)(bm + r) * Kdim + k0 + ld_c * 8);
            cpa16(bS[bsel] + doff, Wt + (size_t)(bn + r) * Kdim + k0 + ld_c * 8);
        }
        CPA_COMMIT();
    };

    load_tile(0, 0);

    for (int t = 0; t < NT; t++) {
        CPA_WAIT0();
        __syncthreads();
        if (t + 1 < NT) load_tile(t + 1, (t + 1) & 1);   // overlaps compute

        const uint32_t aT = aS[t & 1], bT = bS[t & 1];
#pragma unroll
        for (int s = 0; s < 4; s++) {
            const uint32_t aswz = (uint32_t)(((2 * s + da) ^ lr) << 4);
            const uint32_t bswz = (uint32_t)(((2 * s + db) ^ lr) << 4);
            uint32_t a[4][4], bf[4][2];
#pragma unroll
            for (int mi = 0; mi < 4; mi++)
                ldm_x4(a[mi][0], a[mi][1], a[mi][2], a[mi][3],
                       aT + rowA_b + mi * 2048 + aswz);
#pragma unroll
            for (int pi = 0; pi < 2; pi++) {
                uint32_t t0, t1, t2, t3;
                ldm_x4(t0, t1, t2, t3, bT + rowB_b + pi * 2048 + bswz);
                bf[2 * pi][0] = t0; bf[2 * pi][1] = t1;
                bf[2 * pi + 1][0] = t2; bf[2 * pi + 1][1] = t3;
            }
#pragma unroll
            for (int mi = 0; mi < 4; mi++)
#pragma unroll
                for (int ni = 0; ni < 4; ni++) {
                    asm volatile(
                        "mma.sync.aligned.m16n8k16.row.col.f32.f16.f16.f32 "
                        "{%0,%1,%2,%3}, {%4,%5,%6,%7}, {%8,%9}, {%0,%1,%2,%3};"
                        : "+f"(acc[mi][ni][0]), "+f"(acc[mi][ni][1]),
                          "+f"(acc[mi][ni][2]), "+f"(acc[mi][ni][3])
                        : "r"(a[mi][0]), "r"(a[mi][1]), "r"(a[mi][2]), "r"(a[mi][3]),
                          "r"(bf[ni][0]), "r"(bf[ni][1]));
                }
        }
        __syncthreads();
    }

    // ---- epilogue ----
    const int g = lane >> 2, tig = lane & 3;
#pragma unroll
    for (int mi = 0; mi < 4; mi++) {
#pragma unroll
        for (int hf = 0; hf < 2; hf++) {
            int row = bm + warp_m + 16 * mi + g + 8 * hf;
#pragma unroll
            for (int ni = 0; ni < 4; ni++) {
                int col = bn + warp_n + 8 * ni + 2 * tig;
#pragma unroll
                for (int c = 0; c < 2; c++) {
                    float v = acc[mi][ni][2 * hf + c] + bias[col + c];
                    size_t off = (size_t)row * Ndim + col + c;
                    if (EPI == 1) {
                        v = 0.5f * v * (1.0f + erff(v * 0.70710678118654752440f));
                        ((__half*)outv)[off] = __float2half(v);
                    } else if (EPI == 2) {
                        ((float*)outv)[off] = v + res[off];
                    } else {
                        ((float*)outv)[off] = v;
                    }
                }
            }
        }
    }
}

// ---------------------------------------------------------------------------
// Attention: one 128-thread block per (batch, head); padded rows.
// qkv fp32 in, y fp16 out (proj A operand).
// ---------------------------------------------------------------------------
__global__ void attn_kernel(const float* __restrict__ qkv, __half* __restrict__ y) {
    __shared__ float Q[TT][DD + 1], K[TT][DD + 1], V[TT][DD + 1], S[TT][TT + 1];
    int b = blockIdx.x / HH, h = blockIdx.x % HH;
    const float* base = qkv + (size_t)b * TT * 3 * CC + h * DD;

    for (int idx = threadIdx.x; idx < TT * DD; idx += blockDim.x) {
        int t = idx / DD, d = idx % DD;
        const float* p = base + (size_t)t * 3 * CC + d;
        Q[t][d] = p[0];
        K[t][d] = p[CC];
        V[t][d] = p[2 * CC];
    }
    __syncthreads();

    const float scale = 0.125f;
    for (int idx = threadIdx.x; idx < TT * TT; idx += blockDim.x) {
        int tq = idx / TT, tk = idx % TT;
        if (tk <= tq) {
            float s = 0.f;
#pragma unroll
            for (int d = 0; d < DD; d++) s += Q[tq][d] * K[tk][d];
            S[tq][tk] = s * scale;
        }
    }
    __syncthreads();

    if (threadIdx.x < TT) {
        int tq = threadIdx.x;
        float mx = -1e30f;
        for (int tk = 0; tk <= tq; tk++) mx = fmaxf(mx, S[tq][tk]);
        float sum = 0.f;
        for (int tk = 0; tk <= tq; tk++) {
            float e = expf(S[tq][tk] - mx);
            S[tq][tk] = e;
            sum += e;
        }
        float inv = 1.f / sum;
        for (int tk = 0; tk <= tq; tk++) S[tq][tk] *= inv;
    }
    __syncthreads();

    for (int idx = threadIdx.x; idx < TT * DD; idx += blockDim.x) {
        int t = idx / DD, d = idx % DD;
        float o = 0.f;
        for (int tk = 0; tk <= t; tk++) o += S[t][tk] * V[tk][d];
        y[((size_t)b * TT + t) * CC + h * DD + d] = __float2half(o);
    }
}

// ---------------------------------------------------------------------------
// Predictor: xn (fp16) . pred_w (fp32), V=2. One warp per token.
// ---------------------------------------------------------------------------
__global__ void pred_kernel(const __half* __restrict__ xn,
                            const float* __restrict__ pw,
                            const float* __restrict__ pb,
                            float* __restrict__ out) {
    int m = blockIdx.x * 4 + (threadIdx.x >> 5);
    int lane = threadIdx.x & 31;
    const __half* p = xn + (size_t)m * CC;
    float a0 = 0.f, a1 = 0.f;
    for (int c = lane; c < CC; c += 32) {
        float v = __half2float(p[c]);
        a0 += v * pw[c * 2 + 0];
        a1 += v * pw[c * 2 + 1];
    }
#pragma unroll
    for (int o = 16; o > 0; o >>= 1) {
        a0 += __shfl_xor_sync(0xffffffff, a0, o);
        a1 += __shfl_xor_sync(0xffffffff, a1, o);
    }
    if (lane == 0) {
        out[m * 2 + 0] = a0 + pb[0];
        out[m * 2 + 1] = a1 + pb[1];
    }
}

// ---------------------------------------------------------------------------
// Launch
// ---------------------------------------------------------------------------
extern "C" void kernel_launch(void* const* d_in, const int* in_sizes, int n_in,
                              void* d_out, int out_size) {
    const float* x      = (const float*)d_in[0];
    const float* enc_w  = (const float*)d_in[1];
    const float* enc_b  = (const float*)d_in[2];
    const float* wpe    = (const float*)d_in[3];
    const float* ln1_w  = (const float*)d_in[4];
    const float* ln1_b  = (const float*)d_in[5];
    const float* attn_w = (const float*)d_in[6];
    const float* attn_b = (const float*)d_in[7];
    const float* proj_w = (const float*)d_in[8];
    const float* proj_b = (const float*)d_in[9];
    const float* ln2_w  = (const float*)d_in[10];
    const float* ln2_b  = (const float*)d_in[11];
    const float* fc1_w  = (const float*)d_in[12];
    const float* fc1_b  = (const float*)d_in[13];
    const float* fc2_w  = (const float*)d_in[14];
    const float* fc2_b  = (const float*)d_in[15];
    const float* lnf_w  = (const float*)d_in[16];
    const float* lnf_b  = (const float*)d_in[17];
    const float* pred_w = (const float*)d_in[18];
    const float* pred_b = (const float*)d_in[19];

    float *h, *qkv;
    __half *xn, *y, *mid, *wt;
    cudaGetSymbolAddress((void**)&h,   g_h);
    cudaGetSymbolAddress((void**)&xn,  g_xn);
    cudaGetSymbolAddress((void**)&qkv, g_qkv);
    cudaGetSymbolAddress((void**)&y,   g_y);
    cudaGetSymbolAddress((void**)&mid, g_mid);
    cudaGetSymbolAddress((void**)&wt,  g_wt);

    cudaFuncSetAttribute(hgemm_kernel<0>, cudaFuncAttributeMaxDynamicSharedMemorySize, HG_SMEM);
    cudaFuncSetAttribute(hgemm_kernel<1>, cudaFuncAttributeMaxDynamicSharedMemorySize, HG_SMEM);
    cudaFuncSetAttribute(hgemm_kernel<2>, cudaFuncAttributeMaxDynamicSharedMemorySize, HG_SMEM);

    // launch 0: weight transpose + fp16 convert (all 32 matrices)
    wtrans_kernel<<<dim3(64, 64, 32), dim3(32, 8)>>>(attn_w, proj_w, fc1_w, fc2_w, wt);
    // launch 1
    encode_kernel<<<(MTOK * CC + 255) / 256, 256>>>(x, enc_w, enc_b, wpe, h);

    dim3 gQKV(3 * CC / 128, MTOK / 128);   // 12 x 160
    dim3 gC  (CC / 128,     MTOK / 128);   //  4 x 160
    dim3 gFC1(4 * CC / 128, MTOK / 128);   // 16 x 160

    for (int l = 0; l < LL; l++) {
        ln_kernel<<<MTOK, 128>>>(h, ln1_w + l * CC, ln1_b + l * CC, xn);
        hgemm_kernel<0><<<gQKV, 256, HG_SMEM>>>(xn, wt + WATTN_OFF + (size_t)l * CC * 3 * CC,
                                                attn_b + (size_t)l * 3 * CC, nullptr,
                                                (void*)qkv, 3 * CC, CC);
        attn_kernel<<<BB * HH, 128>>>(qkv, y);
        hgemm_kernel<2><<<gC, 256, HG_SMEM>>>(y, wt + WPROJ_OFF + (size_t)l * CC * CC,
                                              proj_b + (size_t)l * CC, h,
                                              (void*)h, CC, CC);
        ln_kernel<<<MTOK, 128>>>(h, ln2_w + l * CC, ln2_b + l * CC, xn);
        hgemm_kernel<1><<<gFC1, 256, HG_SMEM>>>(xn, wt + WFC1_OFF + (size_t)l * CC * 4 * CC,
                                                fc1_b + (size_t)l * 4 * CC, nullptr,
                                                (void*)mid, 4 * CC, CC);
        hgemm_kernel<2><<<gC, 256, HG_SMEM>>>(mid, wt + WFC2_OFF + (size_t)l * 4 * CC * CC,
                                              fc2_b + (size_t)l * CC, h,
                                              (void*)h, CC, 4 * CC);
    }

    ln_kernel<<<MTOK, 128>>>(h, lnf_w, lnf_b, xn);
    pred_kernel<<<MTOK / 4, 128>>>(xn, pred_w, pred_b, (float*)d_out);
}